// round 15
// baseline (speedup 1.0000x reference)
#include <cuda_runtime.h>
#include <cuda_bf16.h>
#include <math.h>
#include <stdint.h>

#define Bv 128
#define Dv 512
#define D2 1024
#define Vv 32000
#define Av 64
#define MAXREC 12
#define KCAP 1664
#define SCALE 0.044194173824159216f
#define NPART (Vv/128)   // 250
#define NCLIN 3072

// k_par roles: 16 mem8 blocks, 250 VQ tiles, 24 clin tiles  -> 290 blocks = ONE wave
#define B_VQ0  16
#define B_CLI0 266
#define NB_PAR 290
#define KTILE 14          // keys per smem tile in mem8

typedef __nv_bfloat16 bf16;

__device__ __align__(16) float g_gr[Bv*Dv], g_gi[Bv*Dv];
__device__ __align__(16) float g_qr[Bv*Dv], g_qi[Bv*Dv], g_kr[Bv*Dv], g_ki[Bv*Dv], g_vr[Bv*Dv], g_vi[Bv*Dv];
__device__ __align__(16) float g_rec[Bv*Dv];
__device__ __align__(16) float g_K[KCAP*Dv], g_Vm[KCAP*Dv];
__device__ float g_kn[KCAP];
__device__ float g_grn[Bv];
__device__ float g_cn[Vv];
__device__ float g_pmin[Bv*NPART];   // [row][part]
__device__ int   g_pidx[Bv*NPART];
__device__ float g_vqrows[MAXREC*Bv];

__device__ __align__(16) bf16 g_zh[Bv*D2], g_zl[Bv*D2];
__device__ __align__(16) bf16 g_wh[NCLIN*D2], g_wl[NCLIN*D2];
__device__ __align__(16) bf16 g_cbh[(size_t)Vv*D2], g_cbl[(size_t)Vv*D2];
__device__ __align__(16) bf16 g_dTh[(size_t)Vv*D2], g_dTl[(size_t)Vv*D2];

template<int NT>
__device__ __forceinline__ float blockSum(float v, float* sh) {
    int tid = threadIdx.x;
    #pragma unroll
    for (int o = 16; o > 0; o >>= 1) v += __shfl_down_sync(0xffffffffu, v, o);
    if ((tid & 31) == 0) sh[tid >> 5] = v;
    __syncthreads();
    float r = (tid < (NT/32)) ? sh[tid] : 0.f;
    if (tid < 32) {
        #pragma unroll
        for (int o = 16; o > 0; o >>= 1) r += __shfl_down_sync(0xffffffffu, r, o);
        if (tid == 0) sh[0] = r;
    }
    __syncthreads();
    float out = sh[0];
    __syncthreads();
    return out;
}

template<int NT>
__device__ __forceinline__ float blockMax(float v, float* sh) {
    int tid = threadIdx.x;
    #pragma unroll
    for (int o = 16; o > 0; o >>= 1) v = fmaxf(v, __shfl_down_sync(0xffffffffu, v, o));
    if ((tid & 31) == 0) sh[tid >> 5] = v;
    __syncthreads();
    float r = (tid < (NT/32)) ? sh[tid] : -3.0e38f;
    if (tid < 32) {
        #pragma unroll
        for (int o = 16; o > 0; o >>= 1) r = fmaxf(r, __shfl_down_sync(0xffffffffu, r, o));
        if (tid == 0) sh[0] = r;
    }
    __syncthreads();
    float out = sh[0];
    __syncthreads();
    return out;
}

__device__ __forceinline__ float4 blockSum4_512(float a, float b, float c, float d, float* sh) {
    int tid = threadIdx.x;
    #pragma unroll
    for (int o = 16; o > 0; o >>= 1) {
        a += __shfl_down_sync(0xffffffffu, a, o);
        b += __shfl_down_sync(0xffffffffu, b, o);
        c += __shfl_down_sync(0xffffffffu, c, o);
        d += __shfl_down_sync(0xffffffffu, d, o);
    }
    int w = tid >> 5;
    if ((tid & 31) == 0) { sh[w] = a; sh[16+w] = b; sh[32+w] = c; sh[48+w] = d; }
    __syncthreads();
    if (tid < 32) {
        float ra = (tid < 16) ? sh[tid]    : 0.f;
        float rb = (tid < 16) ? sh[16+tid] : 0.f;
        float rc = (tid < 16) ? sh[32+tid] : 0.f;
        float rd = (tid < 16) ? sh[48+tid] : 0.f;
        #pragma unroll
        for (int o = 8; o > 0; o >>= 1) {
            ra += __shfl_down_sync(0xffffffffu, ra, o);
            rb += __shfl_down_sync(0xffffffffu, rb, o);
            rc += __shfl_down_sync(0xffffffffu, rc, o);
            rd += __shfl_down_sync(0xffffffffu, rd, o);
        }
        if (tid == 0) { sh[0] = ra; sh[1] = rb; sh[2] = rc; sh[3] = rd; }
    }
    __syncthreads();
    float4 out = make_float4(sh[0], sh[1], sh[2], sh[3]);
    __syncthreads();
    return out;
}

__device__ __forceinline__ float2 blockSum2_512(float a, float b, float* sh) {
    int tid = threadIdx.x;
    #pragma unroll
    for (int o = 16; o > 0; o >>= 1) {
        a += __shfl_down_sync(0xffffffffu, a, o);
        b += __shfl_down_sync(0xffffffffu, b, o);
    }
    int w = tid >> 5;
    if ((tid & 31) == 0) { sh[w] = a; sh[16+w] = b; }
    __syncthreads();
    if (tid < 32) {
        float ra = (tid < 16) ? sh[tid]    : 0.f;
        float rb = (tid < 16) ? sh[16+tid] : 0.f;
        #pragma unroll
        for (int o = 8; o > 0; o >>= 1) {
            ra += __shfl_down_sync(0xffffffffu, ra, o);
            rb += __shfl_down_sync(0xffffffffu, rb, o);
        }
        if (tid == 0) { sh[0] = ra; sh[1] = rb; }
    }
    __syncthreads();
    float2 out = make_float2(sh[0], sh[1]);
    __syncthreads();
    return out;
}

__device__ __forceinline__ void splitStore(float v, bf16* ph, bf16* pl) {
    bf16 h = __float2bfloat16(v);
    *ph = h;
    *pl = __float2bfloat16(v - __bfloat162float(h));
}

__device__ __forceinline__ void updMin(float v, int ix, float& bv, int& bi) {
    if (v < bv || (v == bv && ix < bi)) { bv = v; bi = ix; }
}

// ===== merged prep =====
__global__ void k_prep(const float* cb, const float* W,
                       const int* x, const float* embW, const float* mk, const float* mv,
                       const float* Wqr, const float* Wqi, const float* Wkr,
                       const float* Wki, const float* Wvr, const float* Wvi) {
    __shared__ float sh[8];
    __shared__ float tile[32][33];
    int bid = blockIdx.x, tid = threadIdx.x;
    if (bid < Vv) {
        int j = bid;
        const float* c = cb + (size_t)j * D2;
        float s = 0.f;
        for (int k = tid; k < D2; k += 256) {
            float v = c[k];
            s += v*v;
            splitStore(v, &g_cbh[(size_t)j*D2+k], &g_cbl[(size_t)j*D2+k]);
        }
        float tot = blockSum<256>(s, sh);
        if (tid == 0) g_cn[j] = tot;
    } else if (bid < 2*Vv) {
        int idx = bid - Vv;
        int n0 = (idx % 1000) * 32, k0 = (idx / 1000) * 32;
        int tx = tid & 31, ty = tid >> 5;
        for (int r = ty; r < 32; r += 8)
            tile[r][tx] = W[(size_t)(k0+r)*Vv + n0 + tx];
        __syncthreads();
        for (int r = ty; r < 32; r += 8) {
            float v = tile[tx][r];
            size_t o = (size_t)(n0+r)*D2 + k0 + tx;
            splitStore(v, &g_dTh[o], &g_dTl[o]);
        }
    } else if (bid < 2*Vv + Bv) {
        int i = bid - 2*Vv;
        const float* e = embW + (size_t)x[i] * D2;
        float sq = 0.f;
        for (int d = tid; d < Dv; d += 256) {
            float r = e[d], im = e[Dv+d];
            g_gr[i*Dv+d] = r; g_gi[i*Dv+d] = im;
            splitStore(r,  &g_zh[i*D2+d],    &g_zl[i*D2+d]);
            splitStore(im, &g_zh[i*D2+Dv+d], &g_zl[i*D2+Dv+d]);
            sq += r*r;
        }
        float tot = blockSum<256>(sq, sh);
        if (tid == 0) g_grn[i] = 1.f / fmaxf(sqrtf(tot), 1e-12f);
    } else if (bid < 2*Vv + 2*Bv) {
        int i = bid - 2*Vv - Bv;
        float s = 0.f;
        for (int d = tid; d < Dv; d += 256) {
            float k = mk[i*Dv+d];
            g_K[(1536+i)*Dv+d] = k;
            g_Vm[(1536+i)*Dv+d] = mv[i*Dv+d];
            s += k*k;
        }
        float tot = blockSum<256>(s, sh);
        if (tid == 0) g_kn[1536+i] = 1.f / fmaxf(sqrtf(tot), 1e-12f);
    } else {
        int n = (bid - 2*Vv - 2*Bv) * 2 + (tid >> 7);
        int tl = tid & 127;
        int grp = n >> 9, c = n & 511;
        const float *s1, *s2; float sg2;
        switch (grp) {
            case 0: s1=Wqr; s2=Wqi; sg2=-1.f; break;
            case 1: s1=Wqi; s2=Wqr; sg2= 1.f; break;
            case 2: s1=Wkr; s2=Wki; sg2=-1.f; break;
            case 3: s1=Wki; s2=Wkr; sg2= 1.f; break;
            case 4: s1=Wvr; s2=Wvi; sg2=-1.f; break;
            default:s1=Wvi; s2=Wvr; sg2= 1.f; break;
        }
        for (int k = tl; k < Dv; k += 128) {
            float v1 = s1[c*Dv + k];
            float v2 = sg2 * s2[c*Dv + k];
            splitStore(v1, &g_wh[n*D2+k],    &g_wl[n*D2+k]);
            splitStore(v2, &g_wh[n*D2+Dv+k], &g_wl[n*D2+Dv+k]);
        }
    }
}
#define NB_PREP (2*Vv + 2*Bv + NCLIN/2)

#define MMA16816(c, a, b) \
    asm volatile("mma.sync.aligned.m16n8k16.row.col.f32.bf16.bf16.f32 " \
        "{%0,%1,%2,%3},{%4,%5,%6,%7},{%8,%9},{%0,%1,%2,%3};" \
        : "+f"(c[0]), "+f"(c[1]), "+f"(c[2]), "+f"(c[3]) \
        : "r"(a[0]), "r"(a[1]), "r"(a[2]), "r"(a[3]), "r"(b[0]), "r"(b[1]))

#define LDSM4(d0, d1, d2, d3, addr) \
    asm volatile("ldmatrix.sync.aligned.m8n8.x4.shared.b16 {%0,%1,%2,%3}, [%4];" \
        : "=r"(d0), "=r"(d1), "=r"(d2), "=r"(d3) : "r"(addr))

#define CPA16(dst, src) \
    asm volatile("cp.async.cg.shared.global [%0], [%1], 16;" :: "r"(dst), "l"(src))

#define TP 40
#define SARR (128*TP*2)
#define SSTG (4*SARR)
#define SMEM_MMA (2*SSTG)

// MODE 0: clin scatter   MODE 1: vq argmin   MODE 2: dec (+bias -> out)
template<int MODE>
__device__ __forceinline__ void mma_tile(char* dsm, int n0,
                                         const bf16* __restrict__ Bhp,
                                         const bf16* __restrict__ Blp, int pbid,
                                         const float* __restrict__ bias,
                                         float* __restrict__ out) {
    const uint32_t sb = (uint32_t)__cvta_generic_to_shared(dsm);
    const int tid = threadIdx.x;
    const int wid = tid >> 5, lane = tid & 31;
    const int wm = wid >> 2, wn = wid & 3;
    const int g = lane >> 2, tig = lane & 3;
    const int tg = lane >> 3, tr = lane & 7;
    const int a_row = ((tg & 1) << 3) + tr;
    const int a_col = (tg >> 1) << 3;
    const int b_row = ((tg >> 1) << 3) + tr;
    const int b_col = (tg & 1) << 3;

    float acc[4][4][4];
    #pragma unroll
    for (int a = 0; a < 4; a++)
        #pragma unroll
        for (int b = 0; b < 4; b++)
            #pragma unroll
            for (int c = 0; c < 4; c++) acc[a][b][c] = 0.f;

    const int zr0 = tid >> 2,         zs0 = (tid & 3) * 8;
    const int zr1 = (tid + 256) >> 2, zs1 = ((tid + 256) & 3) * 8;

    auto loadStage = [&](int stg, int k0) {
        uint32_t s0 = sb + stg * SSTG;
        CPA16(s0 +            (zr0*TP + zs0)*2, &g_zh[(size_t)zr0*D2 + k0 + zs0]);
        CPA16(s0 +            (zr1*TP + zs1)*2, &g_zh[(size_t)zr1*D2 + k0 + zs1]);
        CPA16(s0 +   SARR +   (zr0*TP + zs0)*2, &g_zl[(size_t)zr0*D2 + k0 + zs0]);
        CPA16(s0 +   SARR +   (zr1*TP + zs1)*2, &g_zl[(size_t)zr1*D2 + k0 + zs1]);
        CPA16(s0 + 2*SARR +   (zr0*TP + zs0)*2, &Bhp[(size_t)(n0+zr0)*D2 + k0 + zs0]);
        CPA16(s0 + 2*SARR +   (zr1*TP + zs1)*2, &Bhp[(size_t)(n0+zr1)*D2 + k0 + zs1]);
        CPA16(s0 + 3*SARR +   (zr0*TP + zs0)*2, &Blp[(size_t)(n0+zr0)*D2 + k0 + zs0]);
        CPA16(s0 + 3*SARR +   (zr1*TP + zs1)*2, &Blp[(size_t)(n0+zr1)*D2 + k0 + zs1]);
        asm volatile("cp.async.commit_group;");
    };

    loadStage(0, 0);

    const int NKC = D2 / 32;
    for (int kc = 0; kc < NKC; kc++) {
        if (kc + 1 < NKC) {
            loadStage((kc + 1) & 1, (kc + 1) * 32);
            asm volatile("cp.async.wait_group 1;");
        } else {
            asm volatile("cp.async.wait_group 0;");
        }
        __syncthreads();

        const uint32_t s0 = sb + (kc & 1) * SSTG;
        #pragma unroll
        for (int sub = 0; sub < 2; sub++) {
            const int kb = sub * 16;
            uint32_t af[4][4], bh2[4][2], bl2[4][2];
            #pragma unroll
            for (int fm = 0; fm < 4; fm++) {
                uint32_t addr = s0 + ((wm*64 + fm*16 + a_row)*TP + kb + a_col)*2;
                LDSM4(af[fm][0], af[fm][1], af[fm][2], af[fm][3], addr);
            }
            #pragma unroll
            for (int p = 0; p < 2; p++) {
                uint32_t addr = s0 + 2*SARR + ((wn*32 + p*16 + b_row)*TP + kb + b_col)*2;
                LDSM4(bh2[2*p][0], bh2[2*p][1], bh2[2*p+1][0], bh2[2*p+1][1], addr);
            }
            #pragma unroll
            for (int fm = 0; fm < 4; fm++)
                #pragma unroll
                for (int fn = 0; fn < 4; fn++) MMA16816(acc[fm][fn], af[fm], bh2[fn]);
            #pragma unroll
            for (int p = 0; p < 2; p++) {
                uint32_t addr = s0 + 3*SARR + ((wn*32 + p*16 + b_row)*TP + kb + b_col)*2;
                LDSM4(bl2[2*p][0], bl2[2*p][1], bl2[2*p+1][0], bl2[2*p+1][1], addr);
            }
            #pragma unroll
            for (int fm = 0; fm < 4; fm++)
                #pragma unroll
                for (int fn = 0; fn < 4; fn++) MMA16816(acc[fm][fn], af[fm], bl2[fn]);
            #pragma unroll
            for (int fm = 0; fm < 4; fm++) {
                uint32_t addr = s0 + SARR + ((wm*64 + fm*16 + a_row)*TP + kb + a_col)*2;
                LDSM4(af[fm][0], af[fm][1], af[fm][2], af[fm][3], addr);
            }
            #pragma unroll
            for (int fm = 0; fm < 4; fm++)
                #pragma unroll
                for (int fn = 0; fn < 4; fn++) MMA16816(acc[fm][fn], af[fm], bh2[fn]);
        }
        __syncthreads();
    }

    if (MODE == 0) {
        float* outs[6] = {g_qr, g_qi, g_kr, g_ki, g_vr, g_vi};
        #pragma unroll
        for (int fm = 0; fm < 4; fm++) {
            int r = wm*64 + fm*16 + g;
            #pragma unroll
            for (int fn = 0; fn < 4; fn++) {
                int gcol = n0 + wn*32 + fn*8 + tig*2;
                float* dst = outs[gcol >> 9];
                int c = gcol & 511;
                *(float2*)&dst[r*Dv + c]     = make_float2(acc[fm][fn][0], acc[fm][fn][1]);
                *(float2*)&dst[(r+8)*Dv + c] = make_float2(acc[fm][fn][2], acc[fm][fn][3]);
            }
        }
    } else if (MODE == 2) {
        #pragma unroll
        for (int fm = 0; fm < 4; fm++) {
            int r = wm*64 + fm*16 + g;
            #pragma unroll
            for (int fn = 0; fn < 4; fn++) {
                int gcol = n0 + wn*32 + fn*8 + tig*2;
                float b0 = bias[gcol], b1 = bias[gcol+1];
                *(float2*)&out[(size_t)r*Vv + gcol] =
                    make_float2(acc[fm][fn][0] + b0, acc[fm][fn][1] + b1);
                *(float2*)&out[(size_t)(r+8)*Vv + gcol] =
                    make_float2(acc[fm][fn][2] + b0, acc[fm][fn][3] + b1);
            }
        }
    } else {
        float* minv = (float*)dsm;
        int*   mini = (int*)(dsm + 128*4*sizeof(float));
        #pragma unroll
        for (int fm = 0; fm < 4; fm++) {
            int r0 = wm*64 + fm*16 + g;
            float bv0 = 3.0e38f, bv1 = 3.0e38f;
            int bi0 = 0x7fffffff, bi1 = 0x7fffffff;
            #pragma unroll
            for (int fn = 0; fn < 4; fn++) {
                int gcol = n0 + wn*32 + fn*8 + tig*2;
                float cn0 = g_cn[gcol], cn1 = g_cn[gcol+1];
                updMin(cn0 - 2.f*acc[fm][fn][0], gcol,   bv0, bi0);
                updMin(cn1 - 2.f*acc[fm][fn][1], gcol+1, bv0, bi0);
                updMin(cn0 - 2.f*acc[fm][fn][2], gcol,   bv1, bi1);
                updMin(cn1 - 2.f*acc[fm][fn][3], gcol+1, bv1, bi1);
            }
            #pragma unroll
            for (int o = 1; o <= 2; o <<= 1) {
                float ov = __shfl_xor_sync(0xffffffffu, bv0, o);
                int   oi = __shfl_xor_sync(0xffffffffu, bi0, o);
                updMin(ov, oi, bv0, bi0);
                ov = __shfl_xor_sync(0xffffffffu, bv1, o);
                oi = __shfl_xor_sync(0xffffffffu, bi1, o);
                updMin(ov, oi, bv1, bi1);
            }
            if (tig == 0) {
                minv[r0*4 + wn] = bv0; mini[r0*4 + wn] = bi0;
                minv[(r0+8)*4 + wn] = bv1; mini[(r0+8)*4 + wn] = bi1;
            }
        }
        __syncthreads();
        if (tid < 128) {
            float bv = 3.0e38f; int bi = 0x7fffffff;
            #pragma unroll
            for (int w = 0; w < 4; w++) updMin(minv[tid*4+w], mini[tid*4+w], bv, bi);
            g_pmin[tid*NPART + pbid] = bv;
            g_pidx[tid*NPART + pbid] = bi;
        }
    }
}

// ===== k_par: 16 mem8 blocks (online softmax over 8 rows) + 250 VQ + 24 clin =====
__global__ __launch_bounds__(256, 2) void k_par(int off, int M) {
    extern __shared__ __align__(16) char dsm[];
    int bid = blockIdx.x, tid = threadIdx.x;

    if (bid < B_VQ0) {
        // ---- mem8: 8 rows per block, online softmax, K/V tiled through smem ----
        float* sg  = (float*)dsm;                 // 8 x 512
        float* kt  = sg + 8*Dv;                   // KTILE x 512
        float* vt  = kt + KTILE*Dv;               // KTILE x 512
        float* skn = vt + KTILE*Dv;               // KTILE
        const int i0 = bid * 8;
        const int r = tid >> 5, lane = tid & 31;  // warp = row

        for (int idx = tid; idx < 8*Dv; idx += 256)
            sg[idx] = g_gr[(i0 + (idx >> 9))*Dv + (idx & 511)];
        __syncthreads();
        const float rni = g_grn[i0 + r];

        float mstate = -3.0e38f, ssum = 0.f;
        float acc[16];
        #pragma unroll
        for (int u = 0; u < 16; u++) acc[u] = 0.f;

        for (int t0 = 0; t0 < M; t0 += KTILE) {
            int cnt = min(KTILE, M - t0);
            __syncthreads();
            for (int idx = tid; idx < cnt*128; idx += 256) {
                int row = idx >> 7, c4 = idx & 127;
                ((float4*)kt)[row*128 + c4] = *(const float4*)&g_K [(size_t)(off+t0+row)*Dv + c4*4];
                ((float4*)vt)[row*128 + c4] = *(const float4*)&g_Vm[(size_t)(off+t0+row)*Dv + c4*4];
            }
            if (tid < cnt) skn[tid] = g_kn[off + t0 + tid];
            __syncthreads();
            for (int k = 0; k < cnt; k++) {
                float p = 0.f;
                #pragma unroll
                for (int u = 0; u < 16; u++)
                    p += sg[r*Dv + lane + 32*u] * kt[k*Dv + lane + 32*u];
                #pragma unroll
                for (int o = 16; o > 0; o >>= 1) p += __shfl_xor_sync(0xffffffffu, p, o);
                float l = 5.f * p * rni * skn[k];
                if (l > mstate) {
                    float sc = expf(mstate - l);
                    ssum *= sc;
                    #pragma unroll
                    for (int u = 0; u < 16; u++) acc[u] *= sc;
                    mstate = l;
                }
                float wv = expf(l - mstate);
                ssum += wv;
                #pragma unroll
                for (int u = 0; u < 16; u++) acc[u] += wv * vt[k*Dv + lane + 32*u];
            }
        }
        float inv = 1.f / ssum;
        #pragma unroll
        for (int u = 0; u < 16; u++)
            g_rec[(i0 + r)*Dv + lane + 32*u] = acc[u] * inv;
        // push pre-update gr into rows [off-128, off)
        {
            int noff = off - 128;
            #pragma unroll
            for (int u = 0; u < 16; u++) {
                float v = sg[r*Dv + lane + 32*u];
                g_K [(size_t)(noff + i0 + r)*Dv + lane + 32*u] = v;
                g_Vm[(size_t)(noff + i0 + r)*Dv + lane + 32*u] = v;
            }
            if (lane == 0) g_kn[noff + i0 + r] = rni;
        }
    } else if (bid < B_CLI0) {
        mma_tile<1>(dsm, (bid - B_VQ0) * 128, g_cbh, g_cbl, bid - B_VQ0, nullptr, nullptr);
    } else {
        mma_tile<0>(dsm, (bid - B_CLI0) * 128, g_wh, g_wl, 0, nullptr, nullptr);
    }
}

__global__ __launch_bounds__(256, 2) void k_dec(const float* __restrict__ bias,
                                                float* __restrict__ out) {
    extern __shared__ __align__(16) char dsm[];
    mma_tile<2>(dsm, blockIdx.x * 128, g_dTh, g_dTl, 0, bias, out);
}

// ===== fused per-row kernel, 512 threads: argmin + palette + attention + LN + combine =====
__global__ __launch_bounds__(512) void k_row(const float* lng, const float* lnb,
        const float* pw, const float* pb, const float* cb, const float* sensb,
        const float* memw, const float* memb, const float* semw, const float* semb,
        const float* vis, const float* aud, const float* sw, int t) {
    __shared__ float q[D2];
    __shared__ float sgr[Dv], sgi[Dv];
    __shared__ float part[4][Bv];
    __shared__ float att[Bv];
    __shared__ float sh[64];
    __shared__ float w[4];
    __shared__ float lgv[Av], lga[Av];
    __shared__ float sv[512]; __shared__ int si[512];
    __shared__ int sidx;
    int i = blockIdx.x, tid = threadIdx.x;
    int lane = tid & 31, wd = tid >> 5;

    {
        float bv = 3.0e38f; int bi = 0x7fffffff;
        if (tid < NPART) { bv = g_pmin[i*NPART + tid]; bi = g_pidx[i*NPART + tid]; }
        sv[tid] = bv; si[tid] = bi;
    }
    q[tid]      = g_qr[i*Dv + tid];
    q[Dv + tid] = g_qi[i*Dv + tid];
    sgr[tid] = g_gr[i*Dv + tid];
    sgi[tid] = g_gi[i*Dv + tid];
    __syncthreads();
    #pragma unroll
    for (int s = 256; s >= 32; s >>= 1) {
        if (tid < s) {
            float v = sv[tid+s]; int ix = si[tid+s];
            if (v < sv[tid] || (v == sv[tid] && ix < si[tid])) { sv[tid] = v; si[tid] = ix; }
        }
        __syncthreads();
    }
    if (tid < 32) {
        float bv = sv[tid]; int bi = si[tid];
        #pragma unroll
        for (int o = 16; o > 0; o >>= 1) {
            float ov = __shfl_down_sync(0xffffffffu, bv, o);
            int   oi = __shfl_down_sync(0xffffffffu, bi, o);
            updMin(ov, oi, bv, bi);
        }
        if (tid == 0) sidx = bi;
    }

    // palette logits: warp wd handles vis rows & aud rows [wd*4, wd*4+4)
    #pragma unroll
    for (int j = 0; j < 4; j++) {
        int a = wd*4 + j;
        const float* pv = vis + a*Dv;
        const float* pa = aud + a*Dv;
        float p1 = 0.f, p2 = 0.f;
        #pragma unroll
        for (int u = 0; u < 16; u++) {
            p1 += pv[lane + 32*u] * sgr[lane + 32*u];
            p2 += pa[lane + 32*u] * sgi[lane + 32*u];
        }
        #pragma unroll
        for (int o = 16; o > 0; o >>= 1) {
            p1 += __shfl_down_sync(0xffffffffu, p1, o);
            p2 += __shfl_down_sync(0xffffffffu, p2, o);
        }
        if (lane == 0) { lgv[a] = p1; lga[a] = p2; }
    }

    // attention logits: 4 threads per key
    {
        int j = tid & 127, seg = tid >> 7;
        const float* kv = (seg < 2) ? &g_kr[j*Dv + (seg & 1)*256]
                                    : &g_ki[j*Dv + (seg & 1)*256];
        const float* qv = &q[seg*256];
        float s0 = 0.f, s1 = 0.f;
        for (int k = 0; k < 256; k += 8) {
            float4 a = *(const float4*)&kv[k];
            float4 a2 = *(const float4*)&kv[k+4];
            s0 += qv[k]*a.x + qv[k+1]*a.y + qv[k+2]*a.z + qv[k+3]*a.w;
            s1 += qv[k+4]*a2.x + qv[k+5]*a2.y + qv[k+6]*a2.z + qv[k+7]*a2.w;
        }
        part[seg][j] = s0 + s1;
    }
    __syncthreads();
    float logit = (tid < 128)
        ? (part[0][tid] + part[1][tid] + part[2][tid] + part[3][tid]) * SCALE
        : -3.0e38f;
    float mx = blockMax<512>(logit, sh);
    float e = (tid < 128) ? expf(logit - mx) : 0.f;
    float es = blockSum<512>(e, sh);
    if (tid < 128) att[tid] = e / es;
    if (tid == 0) {
        float m1 = -3.0e38f, m2 = -3.0e38f;
        for (int a = 0; a < Av; a++) { m1 = fmaxf(m1, lgv[a]); m2 = fmaxf(m2, lga[a]); }
        float s1 = 0.f, s2 = 0.f;
        for (int a = 0; a < Av; a++) {
            float e1 = expf(lgv[a]-m1); lgv[a] = e1; s1 += e1;
            float e2 = expf(lga[a]-m2); lga[a] = e2; s2 += e2;
        }
        float i1 = 1.f/s1, i2 = 1.f/s2;
        for (int a = 0; a < Av; a++) { lgv[a] *= i1; lga[a] *= i2; }
    }
    __syncthreads();

    // attn @ [vr|vi]
    float fr = 0.f, fi = 0.f;
    {
        const float* vr = &g_vr[tid];
        const float* vi = &g_vi[tid];
        for (int j = 0; j + 4 <= Bv; j += 4) {
            float w0 = att[j], w1 = att[j+1], w2 = att[j+2], w3 = att[j+3];
            fr += w0*vr[(j)*Dv] + w1*vr[(j+1)*Dv] + w2*vr[(j+2)*Dv] + w3*vr[(j+3)*Dv];
            fi += w0*vi[(j)*Dv] + w1*vi[(j+1)*Dv] + w2*vi[(j+2)*Dv] + w3*vi[(j+3)*Dv];
        }
    }
    // palette responses for dim d = tid
    float vrsp = 0.f, arsp = 0.f;
    for (int a = 0; a < Av; a++) {
        vrsp += lgv[a] * vis[a*Dv + tid];
        arsp += lga[a] * aud[a*Dv + tid];
    }
    // LayerNorm
    float m = blockSum<512>(fr + fi, sh) * (1.f/1024.f);
    float d0 = fr - m, d1 = fi - m;
    float var = blockSum<512>(d0*d0 + d1*d1, sh) * (1.f/1024.f);
    float rstd = rsqrtf(var + 1e-5f);
    int c0 = tid, c2 = Dv + tid;
    const float* c = &cb[(size_t)sidx*D2];
    float yr = d0*rstd*lng[c0] + lnb[c0];
    float yi = d1*rstd*lng[c2] + lnb[c2];
    float recv = g_rec[i*Dv + tid];
    float4 r4 = blockSum4_512(yr*pw[c0] + yi*pw[c2],
                              recv * memw[tid],
                              c[c0]*semw[c0] + c[c2]*semw[c2],
                              vrsp*sw[tid] + arsp*sw[Dv + tid], sh);
    if (tid == 0) {
        float a0 = (r4.x + pb[0]) * 1.25f;
        float a1 = (r4.w + sensb[0]) * 1.25f;
        float a2 = (r4.y + memb[0]) * 1.25f;
        float a3 = (r4.z + semb[0]) * 1.25f;
        float mxx = fmaxf(fmaxf(a0,a1), fmaxf(a2,a3));
        float e0 = expf(a0-mxx), e1 = expf(a1-mxx), e2 = expf(a2-mxx), e3 = expf(a3-mxx);
        float inv = 1.f / (e0+e1+e2+e3);
        w[0]=e0*inv; w[1]=e1*inv; w[2]=e2*inv; w[3]=e3*inv;
    }
    __syncthreads();
    float w0 = w[0], w1 = w[1], w2 = w[2], w3 = w[3];
    int d = tid;
    float ogr = sgr[d], ogi = sgi[d];
    float cr = c[d], ci = c[Dv+d];
    float dr = cr-ogr, di = ci-ogi;
    float vql = dr*dr + di*di;
    float nr = w0*yr + w1*vrsp + w2*recv + w3*cr;
    float ni = w0*yi + w1*arsp          + w3*ci;
    float ngr = 0.6f*ogr + 0.4f*nr, ngi = 0.6f*ogi + 0.4f*ni;
    g_gr[i*Dv+d] = ngr; g_gi[i*Dv+d] = ngi;
    splitStore(ngr, &g_zh[i*D2+d],    &g_zl[i*D2+d]);
    splitStore(ngi, &g_zh[i*D2+Dv+d], &g_zl[i*D2+Dv+d]);
    float2 r2 = blockSum2_512(ngr*ngr, vql, sh);
    if (tid == 0) {
        g_grn[i] = 1.f / fmaxf(sqrtf(r2.x), 1e-12f);
        g_vqrows[t*Bv + i] = r2.y;
    }
}

__global__ void k_fin(float* out) {
    __shared__ float sh[8];
    int tid = threadIdx.x;
    float s = 0.f;
    for (int k = tid; k < MAXREC*Bv; k += 256) s += g_vqrows[k];
    float tot = blockSum<256>(s, sh);
    if (tid == 0) {
        out[(size_t)Bv*Vv]     = 1.25f * tot / 131072.f;
        out[(size_t)Bv*Vv + 1] = (float)MAXREC;
    }
}

extern "C" void kernel_launch(void* const* d_in, const int* in_sizes, int n_in,
                              void* d_out, int out_size) {
    const int*   x    = (const int*)d_in[0];
    const float* embW = (const float*)d_in[1];
    const float* Wqr  = (const float*)d_in[2];
    const float* Wqi  = (const float*)d_in[3];
    const float* Wkr  = (const float*)d_in[4];
    const float* Wki  = (const float*)d_in[5];
    const float* Wvr  = (const float*)d_in[6];
    const float* Wvi  = (const float*)d_in[7];
    const float* lng  = (const float*)d_in[8];
    const float* lnb  = (const float*)d_in[9];
    const float* pw   = (const float*)d_in[10];
    const float* pb   = (const float*)d_in[11];
    const float* vis  = (const float*)d_in[12];
    const float* aud  = (const float*)d_in[13];
    const float* sw   = (const float*)d_in[14];
    const float* sb   = (const float*)d_in[15];
    const float* mk   = (const float*)d_in[16];
    const float* mv   = (const float*)d_in[17];
    const float* memw = (const float*)d_in[18];
    const float* memb = (const float*)d_in[19];
    const float* cb   = (const float*)d_in[20];
    const float* semw = (const float*)d_in[21];
    const float* semb = (const float*)d_in[22];
    const float* decW = (const float*)d_in[23];
    const float* decb = (const float*)d_in[24];
    float* out = (float*)d_out;

    cudaFuncSetAttribute(k_par, cudaFuncAttributeMaxDynamicSharedMemorySize, SMEM_MMA);
    cudaFuncSetAttribute(k_dec, cudaFuncAttributeMaxDynamicSharedMemorySize, SMEM_MMA);

    k_prep<<<NB_PREP, 256>>>(cb, decW, x, embW, mk, mv,
                             Wqr, Wqi, Wkr, Wki, Wvr, Wvi);                     // 0

    for (int t = 0; t < MAXREC; t++) {
        int off = 1536 - 128*t;
        int M   = 128 + 127*t;
        k_par<<<NB_PAR, 256, SMEM_MMA>>>(off, M);                               // 1, 3(t=1), ...
        k_row<<<Bv, 512>>>(lng, lnb, pw, pb, cb, sb, memw, memb, semw, semb,
                           vis, aud, sw, t);
    }

    k_dec<<<NPART, 256, SMEM_MMA>>>(decb, out);
    k_fin<<<1, 256>>>(out);
    (void)in_sizes; (void)n_in; (void)out_size;
}